// round 3
// baseline (speedup 1.0000x reference)
#include <cuda_runtime.h>
#include <math.h>

#define B_SZ 4
#define N_PTS 8192
#define KNN 20
#define NCH 16
#define TILE 2048
#define THREADS 128
#define NBLK ((B_SZ * N_PTS) / THREADS)   // 256 knn blocks

// Scratch (allocations forbidden): per-point 20th distance, per-block partial
// sums (double), and the reduced mean/var.
__device__ float  g_dmax[B_SZ * N_PTS];
__device__ double g_p1[NBLK];
__device__ double g_p2[NBLK];
__device__ float  g_mv[2];

__global__ __launch_bounds__(THREADS) void knn_kernel(const float* __restrict__ x) {
    __shared__ float4 sh[TILE];
    __shared__ double red1[THREADS / 32], red2[THREADS / 32];

    const int blocks_per_batch = N_PTS / THREADS;            // 64
    const int b = blockIdx.x / blocks_per_batch;
    const int n = (blockIdx.x % blocks_per_batch) * THREADS + threadIdx.x;

    const float* xb = x + (size_t)b * 3 * N_PTS;
    const float qx = xb[n];
    const float qy = xb[N_PTS + n];
    const float qz = xb[2 * N_PTS + n];
    const float qsq = fmaf(qx, qx, fmaf(qy, qy, qz * qz));

    // top-20 maintained in e-space: e = |p|^2 - 2 q.p  (= d2 - qsq, constant
    // per-thread offset -> identical ordering, cheaper hot loop)
    const float INF = __int_as_float(0x7f800000);
    float r[KNN];
#pragma unroll
    for (int k = 0; k < KNN; k++) r[k] = INF;

    for (int t = 0; t < N_PTS; t += TILE) {
        __syncthreads();
        for (int i = threadIdx.x; i < TILE; i += THREADS) {
            float px = xb[t + i];
            float py = xb[N_PTS + t + i];
            float pz = xb[2 * N_PTS + t + i];
            float psq = fmaf(px, px, fmaf(py, py, pz * pz));
            sh[i] = make_float4(-2.f * px, -2.f * py, -2.f * pz, psq);
        }
        __syncthreads();

#pragma unroll 16
        for (int i = 0; i < TILE; i++) {
            float4 p = sh[i];  // uniform address -> LDS.128 broadcast
            float e = fmaf(qx, p.x, fmaf(qy, p.y, fmaf(qz, p.z, p.w)));
            if (e < r[KNN - 1]) {   // divergent: insert issues iff >=1 lane takes it
                // parallel sorted-insert (depth 2): a[k] = min(a[k], max(a[k-1], e))
#pragma unroll
                for (int k = KNN - 1; k >= 1; k--)
                    r[k] = fminf(r[k], fmaxf(r[k - 1], e));
                r[0] = fminf(r[0], e);
            }
        }
    }

    // finalize: back to d2-space, clamp, sqrt, accumulate stats in double
    double s1 = 0.0, s2 = 0.0;
#pragma unroll
    for (int k = 0; k < KNN; k++) {
        float d2 = fmaxf(r[k] + qsq, 0.f);
        float d = sqrtf(d2);
        s1 += (double)d;
        s2 += (double)d2;
    }
    g_dmax[b * N_PTS + n] = sqrtf(fmaxf(r[KNN - 1] + qsq, 0.f));

#pragma unroll
    for (int o = 16; o > 0; o >>= 1) {
        s1 += __shfl_xor_sync(0xffffffffu, s1, o);
        s2 += __shfl_xor_sync(0xffffffffu, s2, o);
    }
    int w = threadIdx.x >> 5;
    if ((threadIdx.x & 31) == 0) { red1[w] = s1; red2[w] = s2; }
    __syncthreads();
    if (threadIdx.x == 0) {
        double a = 0.0, c = 0.0;
#pragma unroll
        for (int i = 0; i < THREADS / 32; i++) { a += red1[i]; c += red2[i]; }
        g_p1[blockIdx.x] = a;
        g_p2[blockIdx.x] = c;
    }
}

__global__ void stats_kernel() {
    // one block, 128 threads: reduce 256 per-block partials -> mean, biased var
    __shared__ double sr1[4], sr2[4];
    int t = threadIdx.x;
    double v1 = g_p1[t] + g_p1[t + 128];
    double v2 = g_p2[t] + g_p2[t + 128];
#pragma unroll
    for (int o = 16; o > 0; o >>= 1) {
        v1 += __shfl_xor_sync(0xffffffffu, v1, o);
        v2 += __shfl_xor_sync(0xffffffffu, v2, o);
    }
    if ((t & 31) == 0) { sr1[t >> 5] = v1; sr2[t >> 5] = v2; }
    __syncthreads();
    if (t == 0) {
        double s1 = sr1[0] + sr1[1] + sr1[2] + sr1[3];
        double s2 = sr2[0] + sr2[1] + sr2[2] + sr2[3];
        const double M = (double)(B_SZ * N_PTS * KNN);
        double m = s1 / M;
        double var = s2 / M - m * m;
        if (var < 0.0) var = 0.0;
        g_mv[0] = (float)m;
        g_mv[1] = (float)var;
    }
}

__global__ __launch_bounds__(256) void out_kernel(const float* __restrict__ conv_w,
                                                  const float* __restrict__ gamma,
                                                  const float* __restrict__ beta,
                                                  float* __restrict__ out) {
    __shared__ float s_s[NCH], s_t[NCH];
    if (threadIdx.x < NCH) {
        int c = threadIdx.x;
        float m = g_mv[0];
        float v = g_mv[1];
        float w = conv_w[c];
        float s = gamma[c] * w * rsqrtf(fmaf(w * w, v, 1e-5f));
        s_s[c] = s;
        s_t[c] = beta[c] - s * m;   // y = s*knn + (beta - s*m); conv_b cancels in BN
    }
    __syncthreads();

    int q = blockIdx.x * blockDim.x + threadIdx.x;   // 0 .. B*N-1
    int b = q / N_PTS, n = q % N_PTS;
    float dmax = g_dmax[q];
#pragma unroll
    for (int c = 0; c < NCH; c++) {
        float s = s_s[c];
        float knn = (s >= 0.f) ? dmax : 0.f;  // min knn is always 0 (self-distance)
        float y = fmaf(s, knn, s_t[c]);
        y = (y >= 0.f) ? y : 0.2f * y;        // LeakyReLU, monotone -> commutes with max_k
        out[((size_t)b * NCH + c) * N_PTS + n] = y;
    }
}

extern "C" void kernel_launch(void* const* d_in, const int* in_sizes, int n_in,
                              void* d_out, int out_size) {
    const float* x      = (const float*)d_in[0];
    const float* conv_w = (const float*)d_in[1];
    // d_in[2] = conv_b: cancels analytically in training-mode BN, unused
    const float* gamma  = (const float*)d_in[3];
    const float* beta   = (const float*)d_in[4];
    float* out = (float*)d_out;

    knn_kernel<<<NBLK, THREADS>>>(x);
    stats_kernel<<<1, 128>>>();
    out_kernel<<<(B_SZ * N_PTS) / 256, 256>>>(conv_w, gamma, beta, out);
}

// round 4
// speedup vs baseline: 1.3032x; 1.3032x over previous
#include <cuda_runtime.h>
#include <math.h>

#define B_SZ 4
#define N_PTS 8192
#define KNN 20
#define NCH 16
#define TILE 1024
#define THREADS 128
#define DQ 48                              // per-lane buffer depth
#define NBLK ((B_SZ * N_PTS) / THREADS)    // 256 knn blocks

__device__ float  g_dmax[B_SZ * N_PTS];
__device__ double g_p1[NBLK];
__device__ double g_p2[NBLK];
__device__ float  g_mv[2];

__device__ __forceinline__ void drain_buf(float (&r)[KNN], const float* mybuf,
                                          int& cnt, float& r19) {
    const float INF = __int_as_float(0x7f800000);
    int jmax = (int)__reduce_max_sync(0xffffffffu, (unsigned)cnt);
    for (int j = 0; j < jmax; j++) {            // warp-uniform loop
        float v = mybuf[j * 32];                // conflict-free: lane-strided
        v = (j < cnt) ? v : INF;
        // parallel sorted-insert: a[k] = min(a[k], max(a[k-1], v))
#pragma unroll
        for (int k = KNN - 1; k >= 1; k--)
            r[k] = fminf(r[k], fmaxf(r[k - 1], v));
        r[0] = fminf(r[0], v);
    }
    cnt = 0;
    r19 = r[KNN - 1];
}

__global__ __launch_bounds__(THREADS) void knn_kernel(const float* __restrict__ x) {
    __shared__ float4 sh[TILE];                       // 16 KB
    __shared__ float  buf[(THREADS / 32) * 32 * DQ];  // 24 KB, per-lane stacks
    __shared__ double red1[THREADS / 32], red2[THREADS / 32];

    const int warp = threadIdx.x >> 5, lane = threadIdx.x & 31;
    float* mybuf = buf + warp * 32 * DQ + lane;       // slot j -> mybuf[j*32]

    const int blocks_per_batch = N_PTS / THREADS;     // 64
    const int b = blockIdx.x / blocks_per_batch;
    const int n = (blockIdx.x % blocks_per_batch) * THREADS + threadIdx.x;

    const float* xb = x + (size_t)b * 3 * N_PTS;
    const float qx = xb[n];
    const float qy = xb[N_PTS + n];
    const float qz = xb[2 * N_PTS + n];
    const float qsq = fmaf(qx, qx, fmaf(qy, qy, qz * qz));

    // top-20 in e-space: e = |p|^2 - 2 q.p = d2 - qsq (order-preserving)
    const float INF = __int_as_float(0x7f800000);
    float r[KNN];
#pragma unroll
    for (int k = 0; k < KNN; k++) r[k] = INF;
    float r19 = INF;   // stale threshold: refreshed at drains (conservative)
    int cnt = 0;

    for (int t = 0; t < N_PTS; t += TILE) {
        __syncthreads();
        for (int i = threadIdx.x; i < TILE; i += THREADS) {
            float px = xb[t + i];
            float py = xb[N_PTS + t + i];
            float pz = xb[2 * N_PTS + t + i];
            float psq = fmaf(px, px, fmaf(py, py, pz * pz));
            sh[i] = make_float4(-2.f * px, -2.f * py, -2.f * pz, psq);
        }
        __syncthreads();

        for (int i = 0; i < TILE; i += 8) {
            // warp-uniform drain check: group of 8 can add at most 8 per lane
            if (__any_sync(0xffffffffu, cnt >= DQ - 8))
                drain_buf(r, mybuf, cnt, r19);
#pragma unroll
            for (int u = 0; u < 8; u++) {
                float4 p = sh[i + u];     // uniform address -> LDS.128 broadcast
                float e = fmaf(qx, p.x, fmaf(qy, p.y, fmaf(qz, p.z, p.w)));
                bool q = e < r19;
                mybuf[cnt * 32] = e;      // unconditional; commits only if q
                cnt += (int)q;
            }
        }
    }
    drain_buf(r, mybuf, cnt, r19);        // tail drain

    // finalize: back to d2-space, clamp, sqrt, accumulate stats in double
    double s1 = 0.0, s2 = 0.0;
#pragma unroll
    for (int k = 0; k < KNN; k++) {
        float d2 = fmaxf(r[k] + qsq, 0.f);
        float d = sqrtf(d2);
        s1 += (double)d;
        s2 += (double)d2;
    }
    g_dmax[b * N_PTS + n] = sqrtf(fmaxf(r[KNN - 1] + qsq, 0.f));

#pragma unroll
    for (int o = 16; o > 0; o >>= 1) {
        s1 += __shfl_xor_sync(0xffffffffu, s1, o);
        s2 += __shfl_xor_sync(0xffffffffu, s2, o);
    }
    if (lane == 0) { red1[warp] = s1; red2[warp] = s2; }
    __syncthreads();
    if (threadIdx.x == 0) {
        double a = 0.0, c = 0.0;
#pragma unroll
        for (int i = 0; i < THREADS / 32; i++) { a += red1[i]; c += red2[i]; }
        g_p1[blockIdx.x] = a;
        g_p2[blockIdx.x] = c;
    }
}

__global__ void stats_kernel() {
    __shared__ double sr1[4], sr2[4];
    int t = threadIdx.x;
    double v1 = g_p1[t] + g_p1[t + 128];
    double v2 = g_p2[t] + g_p2[t + 128];
#pragma unroll
    for (int o = 16; o > 0; o >>= 1) {
        v1 += __shfl_xor_sync(0xffffffffu, v1, o);
        v2 += __shfl_xor_sync(0xffffffffu, v2, o);
    }
    if ((t & 31) == 0) { sr1[t >> 5] = v1; sr2[t >> 5] = v2; }
    __syncthreads();
    if (t == 0) {
        double s1 = sr1[0] + sr1[1] + sr1[2] + sr1[3];
        double s2 = sr2[0] + sr2[1] + sr2[2] + sr2[3];
        const double M = (double)(B_SZ * N_PTS * KNN);
        double m = s1 / M;
        double var = s2 / M - m * m;
        if (var < 0.0) var = 0.0;
        g_mv[0] = (float)m;
        g_mv[1] = (float)var;
    }
}

__global__ __launch_bounds__(256) void out_kernel(const float* __restrict__ conv_w,
                                                  const float* __restrict__ gamma,
                                                  const float* __restrict__ beta,
                                                  float* __restrict__ out) {
    __shared__ float s_s[NCH], s_t[NCH];
    if (threadIdx.x < NCH) {
        int c = threadIdx.x;
        float m = g_mv[0];
        float v = g_mv[1];
        float w = conv_w[c];
        float s = gamma[c] * w * rsqrtf(fmaf(w * w, v, 1e-5f));
        s_s[c] = s;
        s_t[c] = beta[c] - s * m;   // conv_b cancels in training-mode BN
    }
    __syncthreads();

    int q = blockIdx.x * blockDim.x + threadIdx.x;
    int b = q / N_PTS, n = q % N_PTS;
    float dmax = g_dmax[q];
#pragma unroll
    for (int c = 0; c < NCH; c++) {
        float s = s_s[c];
        float knn = (s >= 0.f) ? dmax : 0.f;  // min knn = 0 (self-distance)
        float y = fmaf(s, knn, s_t[c]);
        y = (y >= 0.f) ? y : 0.2f * y;        // LeakyReLU commutes with max_k
        out[((size_t)b * NCH + c) * N_PTS + n] = y;
    }
}

extern "C" void kernel_launch(void* const* d_in, const int* in_sizes, int n_in,
                              void* d_out, int out_size) {
    const float* x      = (const float*)d_in[0];
    const float* conv_w = (const float*)d_in[1];
    const float* gamma  = (const float*)d_in[3];
    const float* beta   = (const float*)d_in[4];
    float* out = (float*)d_out;

    knn_kernel<<<NBLK, THREADS>>>(x);
    stats_kernel<<<1, 128>>>();
    out_kernel<<<(B_SZ * N_PTS) / 256, 256>>>(conv_w, gamma, beta, out);
}

// round 5
// speedup vs baseline: 1.8256x; 1.4009x over previous
#include <cuda_runtime.h>
#include <math.h>

#define B_SZ 4
#define N_PTS 8192
#define KNN 20
#define NCH 16
#define TILE 1024
#define THREADS 256
#define SPLIT 4
#define QPB (THREADS / SPLIT)              // 64 queries per block
#define DQ 24                              // per-lane buffer depth
#define NBLK ((B_SZ * N_PTS) / QPB)        // 512 knn blocks

__device__ float  g_dmax[B_SZ * N_PTS];
__device__ double g_p1[NBLK];
__device__ double g_p2[NBLK];
__device__ float  g_mv[2];

__device__ __forceinline__ void insert1(float (&r)[KNN], float v) {
#pragma unroll
    for (int k = KNN - 1; k >= 1; k--)
        r[k] = fminf(r[k], fmaxf(r[k - 1], v));
    r[0] = fminf(r[0], v);
}

__device__ __forceinline__ void drain_buf(float (&r)[KNN], const float* mybuf,
                                          int& cnt, float& r19) {
    const float INF = __int_as_float(0x7f800000);
    int jmax = (int)__reduce_max_sync(0xffffffffu, (unsigned)cnt);
    for (int j = 0; j < jmax; j++) {            // warp-uniform loop
        float v = mybuf[j * 32];                // lane-strided: conflict-free
        v = (j < cnt) ? v : INF;
        insert1(r, v);
    }
    cnt = 0;
    r19 = r[KNN - 1];
}

__global__ __launch_bounds__(THREADS, 4) void knn_kernel(const float* __restrict__ x) {
    __shared__ float4 sh[TILE];                       // 16 KB
    __shared__ float  buf[(THREADS / 32) * 32 * DQ];  // 24 KB; reused for merge
    __shared__ double red1[2], red2[2];

    const int warp = threadIdx.x >> 5, lane = threadIdx.x & 31;
    float* mybuf = buf + warp * 32 * DQ + lane;       // slot j -> mybuf[j*32]

    const int ql = threadIdx.x & (QPB - 1);           // local query 0..63
    const int s  = threadIdx.x >> 6;                  // split 0..3 (warp-uniform)

    const int blocks_per_batch = N_PTS / QPB;         // 128
    const int b = blockIdx.x / blocks_per_batch;
    const int n = (blockIdx.x % blocks_per_batch) * QPB + ql;

    const float* xb = x + (size_t)b * 3 * N_PTS;
    const float qx = xb[n];
    const float qy = xb[N_PTS + n];
    const float qz = xb[2 * N_PTS + n];
    const float qsq = fmaf(qx, qx, fmaf(qy, qy, qz * qz));

    // top-20 in e-space: e = |p|^2 - 2 q.p = d2 - qsq (order-preserving)
    const float INF = __int_as_float(0x7f800000);
    float r[KNN];
#pragma unroll
    for (int k = 0; k < KNN; k++) r[k] = INF;
    float r19 = INF;   // stale threshold, refreshed at drains (conservative)
    int cnt = 0;

    for (int t = 0; t < N_PTS; t += TILE) {
        __syncthreads();
        for (int i = threadIdx.x; i < TILE; i += THREADS) {
            float px = xb[t + i];
            float py = xb[N_PTS + t + i];
            float pz = xb[2 * N_PTS + t + i];
            float psq = fmaf(px, px, fmaf(py, py, pz * pz));
            sh[i] = make_float4(-2.f * px, -2.f * py, -2.f * pz, psq);
        }
        __syncthreads();

        const float4* shs = sh + s;        // split s scans i ≡ s (mod 4)
        for (int j = 0; j < TILE / SPLIT; j += 8) {
            if (__any_sync(0xffffffffu, cnt >= DQ - 8))
                drain_buf(r, mybuf, cnt, r19);
#pragma unroll
            for (int u = 0; u < 8; u++) {
                float4 p = shs[(j + u) << 2];   // warp-uniform -> broadcast
                float e = fmaf(qx, p.x, fmaf(qy, p.y, fmaf(qz, p.z, p.w)));
                bool q = e < r19;
                mybuf[cnt * 32] = e;      // unconditional; commits only if q
                cnt += (int)q;
            }
        }
    }
    drain_buf(r, mybuf, cnt, r19);        // tail drain

    // ---- merge the 4 split lists per query (exact top-20 of union) ----
    __syncthreads();                       // buf now free -> merge storage
    float* mbuf = buf;                     // [(s-1)*64 + ql]*20 + k
    if (s >= 1) {
#pragma unroll
        for (int k = 0; k < KNN; k++)
            mbuf[((s - 1) * QPB + ql) * KNN + k] = r[k];
    }
    __syncthreads();

    if (s == 0) {
        for (int m = 0; m < SPLIT - 1; m++)
#pragma unroll
            for (int k = 0; k < KNN; k++)
                insert1(r, mbuf[(m * QPB + ql) * KNN + k]);

        // finalize: back to d2-space, clamp, sqrt, stats in double
        double s1 = 0.0, s2 = 0.0;
#pragma unroll
        for (int k = 0; k < KNN; k++) {
            float d2 = fmaxf(r[k] + qsq, 0.f);
            float d = sqrtf(d2);
            s1 += (double)d;
            s2 += (double)d2;
        }
        g_dmax[b * N_PTS + n] = sqrtf(fmaxf(r[KNN - 1] + qsq, 0.f));

#pragma unroll
        for (int o = 16; o > 0; o >>= 1) {
            s1 += __shfl_xor_sync(0xffffffffu, s1, o);
            s2 += __shfl_xor_sync(0xffffffffu, s2, o);
        }
        if (lane == 0) { red1[warp] = s1; red2[warp] = s2; }  // warps 0,1 only
    }
    __syncthreads();
    if (threadIdx.x == 0) {
        g_p1[blockIdx.x] = red1[0] + red1[1];
        g_p2[blockIdx.x] = red2[0] + red2[1];
    }
}

__global__ void stats_kernel() {
    __shared__ double sr1[4], sr2[4];
    int t = threadIdx.x;
    double v1 = 0.0, v2 = 0.0;
#pragma unroll
    for (int i = 0; i < NBLK / 128; i++) {
        v1 += g_p1[t + i * 128];
        v2 += g_p2[t + i * 128];
    }
#pragma unroll
    for (int o = 16; o > 0; o >>= 1) {
        v1 += __shfl_xor_sync(0xffffffffu, v1, o);
        v2 += __shfl_xor_sync(0xffffffffu, v2, o);
    }
    if ((t & 31) == 0) { sr1[t >> 5] = v1; sr2[t >> 5] = v2; }
    __syncthreads();
    if (t == 0) {
        double s1 = sr1[0] + sr1[1] + sr1[2] + sr1[3];
        double s2 = sr2[0] + sr2[1] + sr2[2] + sr2[3];
        const double M = (double)(B_SZ * N_PTS * KNN);
        double m = s1 / M;
        double var = s2 / M - m * m;
        if (var < 0.0) var = 0.0;
        g_mv[0] = (float)m;
        g_mv[1] = (float)var;
    }
}

__global__ __launch_bounds__(256) void out_kernel(const float* __restrict__ conv_w,
                                                  const float* __restrict__ gamma,
                                                  const float* __restrict__ beta,
                                                  float* __restrict__ out) {
    __shared__ float s_s[NCH], s_t[NCH];
    if (threadIdx.x < NCH) {
        int c = threadIdx.x;
        float m = g_mv[0];
        float v = g_mv[1];
        float w = conv_w[c];
        float s = gamma[c] * w * rsqrtf(fmaf(w * w, v, 1e-5f));
        s_s[c] = s;
        s_t[c] = beta[c] - s * m;   // conv_b cancels in training-mode BN
    }
    __syncthreads();

    int q = blockIdx.x * blockDim.x + threadIdx.x;
    int b = q / N_PTS, n = q % N_PTS;
    float dmax = g_dmax[q];
#pragma unroll
    for (int c = 0; c < NCH; c++) {
        float s = s_s[c];
        float knn = (s >= 0.f) ? dmax : 0.f;  // min knn = 0 (self-distance)
        float y = fmaf(s, knn, s_t[c]);
        y = (y >= 0.f) ? y : 0.2f * y;        // LeakyReLU commutes with max_k
        out[((size_t)b * NCH + c) * N_PTS + n] = y;
    }
}

extern "C" void kernel_launch(void* const* d_in, const int* in_sizes, int n_in,
                              void* d_out, int out_size) {
    const float* x      = (const float*)d_in[0];
    const float* conv_w = (const float*)d_in[1];
    const float* gamma  = (const float*)d_in[3];
    const float* beta   = (const float*)d_in[4];
    float* out = (float*)d_out;

    knn_kernel<<<NBLK, THREADS>>>(x);
    stats_kernel<<<1, 128>>>();
    out_kernel<<<(B_SZ * N_PTS) / 256, 256>>>(conv_w, gamma, beta, out);
}